// round 15
// baseline (speedup 1.0000x reference)
#include <cuda_runtime.h>
#include <cuda_fp16.h>

#define D 128
#define MAX_N 100000
#define MBLK 64            // rows of x per GEMM block
#define PADH 136           // smem row stride in halves

// support = x@W + b, stored fp16 (25.6 MB)
__device__ __half g_support_h[(size_t)MAX_N * D];
// W transposed + converted to fp16: Wt[n][k]
__device__ __half g_Wt_h[D * D];
// CSR row pointers for destination nodes
__device__ int g_rowptr[MAX_N + 1];

// ---------------------------------------------------------------------------
// prep_edges: rowptr (edst sorted -> rp[d] = first edge with dst >= d) AND
// Wt_h[n][k] = fp16(W[k][n]) in one launch (first 16K threads do Wt too).
// ---------------------------------------------------------------------------
__global__ void prep_edges_kernel(const int* __restrict__ edst,
                                  const float* __restrict__ W,
                                  __half* __restrict__ Wt,
                                  int* __restrict__ rp, int E, int N) {
    int e = blockIdx.x * blockDim.x + threadIdx.x;
    if (e < D * D) {
        int k = e >> 7, n = e & 127;
        Wt[n * D + k] = __float2half(W[e]);
    }
    if (e >= E) return;
    int d  = edst[e];
    int dp = (e == 0) ? -1 : edst[e - 1];
    for (int k = dp + 1; k <= d; k++) rp[k] = e;
    if (e == E - 1)
        for (int k = d + 1; k <= N; k++) rp[k] = E;
}

__device__ __forceinline__ void mma_f16(float d[4], unsigned a0, unsigned a1,
                                        unsigned a2, unsigned a3,
                                        unsigned b0, unsigned b1) {
    asm volatile(
        "mma.sync.aligned.m16n8k16.row.col.f32.f16.f16.f32 "
        "{%0,%1,%2,%3}, {%4,%5,%6,%7}, {%8,%9}, {%0,%1,%2,%3};"
        : "+f"(d[0]), "+f"(d[1]), "+f"(d[2]), "+f"(d[3])
        : "r"(a0), "r"(a1), "r"(a2), "r"(a3), "r"(b0), "r"(b1));
}

// ---------------------------------------------------------------------------
// GEMM: support = fp16(x@W + b) via fp16 mma m16n8k16. (Memory-floor bound;
// unchanged from the proven champion.)
// ---------------------------------------------------------------------------
__global__ void __launch_bounds__(256) gemm_mma_kernel(
        const float* __restrict__ x,
        const __half* __restrict__ Wt,
        const float* __restrict__ b,
        __half* __restrict__ sup, int N) {
    extern __shared__ __half smem[];
    __half* sX = smem;                 // 64  x PADH halves
    __half* sW = smem + MBLK * PADH;   // 128 x PADH halves ([n][k])

    const int tid  = threadIdx.x;
    const int lane = tid & 31;
    const int w    = tid >> 5;
    const int wm   = w & 3;
    const int wn   = w >> 2;
    const int g    = lane >> 2;
    const int tig  = lane & 3;

    const int row0 = blockIdx.x * MBLK;

    const uint4* Wv = (const uint4*)Wt;
    #pragma unroll
    for (int i = tid; i < 128 * 16; i += 256) {
        int r = i >> 4, c = i & 15;
        *(uint4*)(sW + r * PADH + c * 8) = Wv[i];
    }
    const float4* xv = (const float4*)x;
    #pragma unroll
    for (int i = tid; i < MBLK * 32; i += 256) {
        int r = i >> 5, c = i & 31;
        float4 v = make_float4(0.f, 0.f, 0.f, 0.f);
        if (row0 + r < N) v = xv[(size_t)(row0 + r) * 32 + c];
        __half2 h0 = __floats2half2_rn(v.x, v.y);
        __half2 h1 = __floats2half2_rn(v.z, v.w);
        uint2 p = make_uint2(*(unsigned*)&h0, *(unsigned*)&h1);
        *(uint2*)(sX + r * PADH + c * 4) = p;
    }
    __syncthreads();

    float acc[8][4];
    #pragma unroll
    for (int t = 0; t < 8; t++)
        #pragma unroll
        for (int j = 0; j < 4; j++) acc[t][j] = 0.f;

    const int ar0 = wm * 16 + g;
    const int ar1 = ar0 + 8;

    #pragma unroll
    for (int k0 = 0; k0 < D; k0 += 16) {
        unsigned a0 = *(const unsigned*)(sX + ar0 * PADH + k0 + 2 * tig);
        unsigned a1 = *(const unsigned*)(sX + ar1 * PADH + k0 + 2 * tig);
        unsigned a2 = *(const unsigned*)(sX + ar0 * PADH + k0 + 2 * tig + 8);
        unsigned a3 = *(const unsigned*)(sX + ar1 * PADH + k0 + 2 * tig + 8);
        #pragma unroll
        for (int t = 0; t < 8; t++) {
            int n0 = wn * 64 + t * 8;
            unsigned b0 = *(const unsigned*)(sW + (n0 + g) * PADH + k0 + 2 * tig);
            unsigned b1 = *(const unsigned*)(sW + (n0 + g) * PADH + k0 + 2 * tig + 8);
            mma_f16(acc[t], a0, a1, a2, a3, b0, b1);
        }
    }

    const int gr0 = row0 + wm * 16 + g;
    const int gr1 = gr0 + 8;
    #pragma unroll
    for (int t = 0; t < 8; t++) {
        int col = wn * 64 + t * 8 + 2 * tig;
        float bx = b[col], by = b[col + 1];
        if (gr0 < N) {
            __half2 h = __floats2half2_rn(acc[t][0] + bx, acc[t][1] + by);
            *(__half2*)(sup + (size_t)gr0 * D + col) = h;
        }
        if (gr1 < N) {
            __half2 h = __floats2half2_rn(acc[t][2] + bx, acc[t][3] + by);
            *(__half2*)(sup + (size_t)gr1 * D + col) = h;
        }
    }
}

// ---------------------------------------------------------------------------
// CSR pull: one warp per destination node (champion structure). Two edges
// per iteration: paired metadata loads (LDG.64 for src pair + weight pair,
// alignment guaranteed by peeling to even e) and dual independent FFMA
// accumulator chains. No shfl, no atomics; one STG.128 per lane per node.
// ---------------------------------------------------------------------------
__global__ void __launch_bounds__(256) scatter_csr_kernel(
        const __half* __restrict__ sup,
        const float* __restrict__ ew,
        const int* __restrict__ esrc,
        const int* __restrict__ rp,
        float* __restrict__ out, int N) {
    const int warp = (blockIdx.x * blockDim.x + threadIdx.x) >> 5;
    const int lane = threadIdx.x & 31;
    if (warp >= N) return;

    const int beg = rp[warp];
    const int end = rp[warp + 1];

    const uint2* supv = (const uint2*)sup;
    float4 accA = make_float4(0.f, 0.f, 0.f, 0.f);
    float4 accB = make_float4(0.f, 0.f, 0.f, 0.f);

    int e = beg;
    // peel to even index (esrc/ew are >=8B aligned at even offsets)
    if ((e & 1) && e < end) {
        const int   s = __ldg(esrc + e);
        const float w = __ldg(ew + e);
        uint2 u = supv[(size_t)s * 32 + lane];
        float2 f0 = __half22float2(*(__half2*)(&u.x));
        float2 f1 = __half22float2(*(__half2*)(&u.y));
        accA.x += w * f0.x; accA.y += w * f0.y;
        accA.z += w * f1.x; accA.w += w * f1.y;
        e++;
    }

    #pragma unroll 2
    for (; e + 2 <= end; e += 2) {
        const int2   ss = __ldg((const int2*)(esrc + e));    // LDG.64
        const float2 ww = __ldg((const float2*)(ew + e));    // LDG.64
        uint2 u0 = supv[(size_t)ss.x * 32 + lane];
        uint2 u1 = supv[(size_t)ss.y * 32 + lane];

        float2 a0 = __half22float2(*(__half2*)(&u0.x));
        float2 a1 = __half22float2(*(__half2*)(&u0.y));
        accA.x += ww.x * a0.x; accA.y += ww.x * a0.y;
        accA.z += ww.x * a1.x; accA.w += ww.x * a1.y;

        float2 b0 = __half22float2(*(__half2*)(&u1.x));
        float2 b1 = __half22float2(*(__half2*)(&u1.y));
        accB.x += ww.y * b0.x; accB.y += ww.y * b0.y;
        accB.z += ww.y * b1.x; accB.w += ww.y * b1.y;
    }

    if (e < end) {   // trailing single edge
        const int   s = __ldg(esrc + e);
        const float w = __ldg(ew + e);
        uint2 u = supv[(size_t)s * 32 + lane];
        float2 f0 = __half22float2(*(__half2*)(&u.x));
        float2 f1 = __half22float2(*(__half2*)(&u.y));
        accA.x += w * f0.x; accA.y += w * f0.y;
        accA.z += w * f1.x; accA.w += w * f1.y;
    }

    float4 r = make_float4(accA.x + accB.x, accA.y + accB.y,
                           accA.z + accB.z, accA.w + accB.w);
    *(float4*)(out + (size_t)warp * D + lane * 4) = r;
}

extern "C" void kernel_launch(void* const* d_in, const int* in_sizes, int n_in,
                              void* d_out, int out_size) {
    const float* x    = (const float*)d_in[0];
    const float* W    = (const float*)d_in[1];
    const float* b    = (const float*)d_in[2];
    const float* ew   = (const float*)d_in[3];
    const int*   esrc = (const int*)d_in[4];
    const int*   edst = (const int*)d_in[5];
    float* out = (float*)d_out;

    const int N = in_sizes[0] / D;
    const int E = in_sizes[3];

    __half* sup = nullptr;
    cudaGetSymbolAddress((void**)&sup, g_support_h);
    __half* Wt = nullptr;
    cudaGetSymbolAddress((void**)&Wt, g_Wt_h);
    int* rp = nullptr;
    cudaGetSymbolAddress((void**)&rp, g_rowptr);

    prep_edges_kernel<<<(E + 255) / 256, 256>>>(edst, W, Wt, rp, E, N);

    const int gemm_smem = (MBLK * PADH + D * PADH) * (int)sizeof(__half); // ~52 KB
    cudaFuncSetAttribute(gemm_mma_kernel, cudaFuncAttributeMaxDynamicSharedMemorySize, gemm_smem);

    const int gemm_blocks = (N + MBLK - 1) / MBLK;
    gemm_mma_kernel<<<gemm_blocks, 256, gemm_smem>>>(x, Wt, b, sup, N);

    // one warp per node, 8 warps per block
    const int scat_blocks = (N + 7) / 8;
    scatter_csr_kernel<<<scat_blocks, 256>>>(sup, ew, esrc, rp, out, N);
}